// round 14
// baseline (speedup 1.0000x reference)
#include <cuda_runtime.h>

#define NB 64
#define LQ 256
#define EE 64
#define HH 64

// Scratch (static __device__ — no allocations allowed)
__device__ float g_vt[NB * LQ * EE];    // vt[n][l][k] = values[k][l][n]   (4 MB)
__device__ float g_attn[NB * EE * EE];  // attn[n][a][b]                   (1 MB)
__device__ float g_M[NB * EE * EE];     // M[n][e][k] = (W @ A_n)[e][k]    (1 MB)

// ---------------------------------------------------------------------------
// K_front: merged launch, 512 blocks.
//   blocks [0,256):   energy Q·K^T + softmax -> g_attn  (n = b>>2, quarter = b&3)
//                     each block: 16 a-rows x 64 b over all 256 l
//   blocks [256,512): transpose values[k][l][n] -> vt[n][l][k]  (one per l)
// Attn: register prefetch of next 32-l chunk + dual accumulator sets.
// ---------------------------------------------------------------------------
__global__ void __launch_bounds__(256) k_front(const float* __restrict__ values,
                                               const float* __restrict__ query,
                                               const float* __restrict__ keys) {
    __shared__ float sh[4160];           // aliased pool (max of both phases)
    const int tid = threadIdx.x;

    if (blockIdx.x >= 256) {
        // ---- transpose phase ----
        float (*tile)[65] = (float(*)[65])sh;
        const int l = blockIdx.x - 256;
#pragma unroll
        for (int i = 0; i < 4; i++) {
            int f = i * 256 + tid;          // float4 index 0..1023
            int k = f >> 4;                 // 0..63
            int n4 = f & 15;                // 0..15
            float4 v = *(const float4*)(values + ((k * LQ + l) * EE) + n4 * 4);
            tile[k][n4 * 4 + 0] = v.x;
            tile[k][n4 * 4 + 1] = v.y;
            tile[k][n4 * 4 + 2] = v.z;
            tile[k][n4 * 4 + 3] = v.w;
        }
        __syncthreads();
#pragma unroll
        for (int i = 0; i < 4; i++) {
            int f = i * 256 + tid;
            int nn = f >> 4;
            int k4 = f & 15;
            float4 v = make_float4(tile[k4 * 4 + 0][nn], tile[k4 * 4 + 1][nn],
                                   tile[k4 * 4 + 2][nn], tile[k4 * 4 + 3][nn]);
            *(float4*)(g_vt + ((nn * LQ + l) * EE) + k4 * 4) = v;
        }
        return;
    }

    // ---- attention phase: block = (n, quarter) ----
    const int n = blockIdx.x >> 2;
    const int qr = blockIdx.x & 3;            // a-rows [qr*16, qr*16+16)
    float (*sE)[68] = (float(*)[68])sh;            // [16][68]  1088 f
    float (*sQ)[16] = (float(*)[16])(sh + 1088);   // [32][16]   512 f
    float (*sK)[64] = (float(*)[64])(sh + 1600);   // [32][64]  2048 f

    const int a = tid >> 4;          // 0..15 (a-row within quarter)
    const int b0 = (tid & 15) * 4;   // 0..60

    // load slots
    const int krow = tid >> 4;       // 0..15 (K rows: krow and krow+16)
    const int kcq = (tid & 15) * 4;  // K col
    const int qrow = tid >> 2;       // 0..31 for tid<128 (Q row)
    const int qcq = (tid & 3) * 4;   // Q col within quarter

    const float* qb = query + n * LQ * EE + qr * 16;
    const float* kb = keys + n * LQ * EE;

    // dual accumulator sets (even/odd lp) -> 8 independent FMA chains
    float e0a = 0.f, e1a = 0.f, e2a = 0.f, e3a = 0.f;
    float e0b = 0.f, e1b = 0.f, e2b = 0.f, e3b = 0.f;

    // prefetch chunk 0
    float4 kreg0 = *(const float4*)(kb + krow * EE + kcq);
    float4 kreg1 = *(const float4*)(kb + (16 + krow) * EE + kcq);
    float4 qreg;
    if (tid < 128) qreg = *(const float4*)(qb + qrow * EE + qcq);

    for (int c = 0; c < 8; c++) {
        *(float4*)&sK[krow][kcq] = kreg0;
        *(float4*)&sK[16 + krow][kcq] = kreg1;
        if (tid < 128) *(float4*)&sQ[qrow][qcq] = qreg;
        __syncthreads();

        if (c < 7) {
            const int l0 = (c + 1) * 32;
            kreg0 = *(const float4*)(kb + (l0 + krow) * EE + kcq);
            kreg1 = *(const float4*)(kb + (l0 + 16 + krow) * EE + kcq);
            if (tid < 128) qreg = *(const float4*)(qb + (l0 + qrow) * EE + qcq);
        }

#pragma unroll
        for (int lp = 0; lp < 32; lp += 2) {
            float qv0 = sQ[lp][a];
            float4 kv0 = *(const float4*)&sK[lp][b0];
            float qv1 = sQ[lp + 1][a];
            float4 kv1 = *(const float4*)&sK[lp + 1][b0];
            e0a += qv0 * kv0.x; e1a += qv0 * kv0.y; e2a += qv0 * kv0.z; e3a += qv0 * kv0.w;
            e0b += qv1 * kv1.x; e1b += qv1 * kv1.y; e2b += qv1 * kv1.z; e3b += qv1 * kv1.w;
        }
        __syncthreads();
    }
    *(float4*)&sE[a][b0] = make_float4(e0a + e0b, e1a + e1b, e2a + e2b, e3a + e3b);
    __syncthreads();

    // softmax: 8 warps x 2 rows each (16 rows in this quarter); hd=1, no scale
    const int w = tid >> 5, lane = tid & 31;
#pragma unroll
    for (int r = 0; r < 2; r++) {
        int row = w * 2 + r;
        float v0 = sE[row][lane];
        float v1 = sE[row][lane + 32];
        float m = fmaxf(v0, v1);
#pragma unroll
        for (int off = 16; off; off >>= 1) m = fmaxf(m, __shfl_xor_sync(0xffffffffu, m, off));
        float e0 = __expf(v0 - m);
        float e1 = __expf(v1 - m);
        float s = e0 + e1;
#pragma unroll
        for (int off = 16; off; off >>= 1) s += __shfl_xor_sync(0xffffffffu, s, off);
        float inv = 1.0f / s;
        float* dst = g_attn + (n * EE + qr * 16 + row) * EE;
        dst[lane] = e0 * inv;
        dst[lane + 32] = e1 * inv;
    }
}

// ---------------------------------------------------------------------------
// K2: M_n[e][k] = sum_e' W[e][e'] * attn[n][e'][k]   (fold fc into attn)
// grid: 64 blocks (one per n)
// ---------------------------------------------------------------------------
__global__ void __launch_bounds__(256) k_M(const float* __restrict__ W) {
    const int n = blockIdx.x;
    __shared__ float sWt[64][68];  // sWt[e'][e] = W[e][e']
    __shared__ float sA[64][68];   // sA[e'][k]
    const int tid = threadIdx.x;
#pragma unroll
    for (int i = 0; i < 16; i++) {
        int idx = i * 256 + tid;
        int r = idx >> 6, c = idx & 63;
        sWt[c][r] = W[idx];                       // transpose W on the fly
        sA[r][c] = g_attn[n * 4096 + idx];
    }
    __syncthreads();
    const int e0 = (tid >> 4) * 4;
    const int k0 = (tid & 15) * 4;
    float acc[4][4] = {};
#pragma unroll
    for (int ep = 0; ep < 64; ep++) {
        float4 wv = *(const float4*)&sWt[ep][e0];
        float4 av = *(const float4*)&sA[ep][k0];
        acc[0][0] += wv.x * av.x; acc[0][1] += wv.x * av.y; acc[0][2] += wv.x * av.z; acc[0][3] += wv.x * av.w;
        acc[1][0] += wv.y * av.x; acc[1][1] += wv.y * av.y; acc[1][2] += wv.y * av.z; acc[1][3] += wv.y * av.w;
        acc[2][0] += wv.z * av.x; acc[2][1] += wv.z * av.y; acc[2][2] += wv.z * av.z; acc[2][3] += wv.z * av.w;
        acc[3][0] += wv.w * av.x; acc[3][1] += wv.w * av.y; acc[3][2] += wv.w * av.z; acc[3][3] += wv.w * av.w;
    }
#pragma unroll
    for (int i = 0; i < 4; i++) {
        *(float4*)(g_M + ((n * 64 + e0 + i) * 64) + k0) =
            make_float4(acc[i][0], acc[i][1], acc[i][2], acc[i][3]);
    }
}

// ---------------------------------------------------------------------------
// K3: tiled GEMV + LayerNorm; writes ONLY the h=0 slice (4 MB).
// grid: 512 blocks = (n, 32-l chunk); 256 threads = (16 l-pairs) x (16 e-quads)
// ---------------------------------------------------------------------------
__global__ void __launch_bounds__(256) k_compute(const float* __restrict__ bias,
                                                 const float* __restrict__ lnw,
                                                 const float* __restrict__ lnb,
                                                 float* __restrict__ out) {
    const int n = blockIdx.x >> 3;
    const int lc = blockIdx.x & 7;
    const int tid = threadIdx.x;

    __shared__ float sMt[64][68];   // sMt[k][e] = M_n[e][k]
    __shared__ float sv[32][68];    // sv[l'][k]
    __shared__ float sy[32][64];    // normalized output tile
    __shared__ float sb[64], sw[64], sbeta[64];

    if (tid < 64) {
        sb[tid] = bias[tid];
        sw[tid] = lnw[tid];
        sbeta[tid] = lnb[tid];
    }

    // Load + transpose M_n (64x64) into sMt[k][e]
    const float* Mn = g_M + n * 4096;
#pragma unroll
    for (int i = 0; i < 16; i++) {
        int idx = i * 256 + tid;
        int e = idx >> 6, k = idx & 63;
        sMt[k][e] = Mn[idx];
    }
    // Load vt tile (32 x 64), coalesced
    const int lbase = lc * 32;
    const float* vtn = g_vt + (n * LQ + lbase) * EE;
#pragma unroll
    for (int i = 0; i < 8; i++) {
        int idx = i * 256 + tid;
        sv[idx >> 6][idx & 63] = vtn[idx];
    }
    __syncthreads();

    // Micro-tile: 2 l-rows x 4 e-cols per thread
    const int r0 = (tid >> 4) * 2;   // 0..30
    const int e0 = (tid & 15) * 4;   // 0..60

    float a00 = 0.f, a01 = 0.f, a02 = 0.f, a03 = 0.f;
    float a10 = 0.f, a11 = 0.f, a12 = 0.f, a13 = 0.f;
#pragma unroll
    for (int k = 0; k < 64; k++) {
        float v0 = sv[r0][k];
        float v1 = sv[r0 + 1][k];
        float4 m = *(const float4*)&sMt[k][e0];
        a00 += v0 * m.x; a01 += v0 * m.y; a02 += v0 * m.z; a03 += v0 * m.w;
        a10 += v1 * m.x; a11 += v1 * m.y; a12 += v1 * m.z; a13 += v1 * m.w;
    }
    // add fc bias before LN
    float b0v = sb[e0], b1v = sb[e0 + 1], b2v = sb[e0 + 2], b3v = sb[e0 + 3];
    a00 += b0v; a01 += b1v; a02 += b2v; a03 += b3v;
    a10 += b0v; a11 += b1v; a12 += b2v; a13 += b3v;

    // LN stats: reduce over the 16 lanes that share a row-pair (offsets 1..8)
    float s0 = (a00 + a01) + (a02 + a03);
    float q0 = (a00 * a00 + a01 * a01) + (a02 * a02 + a03 * a03);
    float s1 = (a10 + a11) + (a12 + a13);
    float q1 = (a10 * a10 + a11 * a11) + (a12 * a12 + a13 * a13);
#pragma unroll
    for (int off = 8; off; off >>= 1) {
        s0 += __shfl_xor_sync(0xffffffffu, s0, off);
        q0 += __shfl_xor_sync(0xffffffffu, q0, off);
        s1 += __shfl_xor_sync(0xffffffffu, s1, off);
        q1 += __shfl_xor_sync(0xffffffffu, q1, off);
    }
    float mu0 = s0 * (1.0f / 64.0f);
    float var0 = q0 * (1.0f / 64.0f) - mu0 * mu0;
    float ri0 = rsqrtf(var0 + 1e-5f);
    float mu1 = s1 * (1.0f / 64.0f);
    float var1 = q1 * (1.0f / 64.0f) - mu1 * mu1;
    float ri1 = rsqrtf(var1 + 1e-5f);

    float w0 = sw[e0], w1 = sw[e0 + 1], w2 = sw[e0 + 2], w3 = sw[e0 + 3];
    float g0 = sbeta[e0], g1 = sbeta[e0 + 1], g2 = sbeta[e0 + 2], g3 = sbeta[e0 + 3];

    *(float4*)&sy[r0][e0] = make_float4((a00 - mu0) * ri0 * w0 + g0,
                                        (a01 - mu0) * ri0 * w1 + g1,
                                        (a02 - mu0) * ri0 * w2 + g2,
                                        (a03 - mu0) * ri0 * w3 + g3);
    *(float4*)&sy[r0 + 1][e0] = make_float4((a10 - mu1) * ri1 * w0 + g0,
                                            (a11 - mu1) * ri1 * w1 + g1,
                                            (a12 - mu1) * ri1 * w2 + g2,
                                            (a13 - mu1) * ri1 * w3 + g3);
    __syncthreads();

    // write h = 0 slice only (coalesced STG.128)
    const float4* sy4 = (const float4*)sy;
    float4* dst = (float4*)out + n * 4096 + lc * 512 + tid;
    dst[0] = sy4[tid];
    dst[256] = sy4[tid + 256];
}

// ---------------------------------------------------------------------------
// K4: broadcast h=0 slice (4 MB) to h = 1..63 (252 MB of streaming writes).
// 256 blocks, 16 KB segment in 4 registers per thread, 63*4 independent
// plain STG.128 per thread (plain stores measured faster than __stcs).
// ---------------------------------------------------------------------------
__global__ void __launch_bounds__(256) k_bcast(float* __restrict__ out) {
    const int tid = threadIdx.x;
    const size_t segOff4 = (size_t)blockIdx.x * 1024;  // float4 units (16KB/block)
    const float4* src = (const float4*)out + segOff4;
    float4 v0 = src[tid];
    float4 v1 = src[tid + 256];
    float4 v2 = src[tid + 512];
    float4 v3 = src[tid + 768];
    float4* dst = (float4*)out + segOff4 + tid;
    const size_t hstride4 = (size_t)NB * LQ * EE / 4;  // 262144 float4 = 4 MB
#pragma unroll 7
    for (int h = 1; h < HH; h++) {
        float4* p = dst + (size_t)h * hstride4;
        p[0] = v0;
        p[256] = v1;
        p[512] = v2;
        p[768] = v3;
    }
}

// ---------------------------------------------------------------------------
extern "C" void kernel_launch(void* const* d_in, const int* in_sizes, int n_in,
                              void* d_out, int out_size) {
    const float* values = (const float*)d_in[0];
    const float* keys   = (const float*)d_in[1];
    const float* query  = (const float*)d_in[2];
    const float* W      = (const float*)d_in[3];
    const float* b      = (const float*)d_in[4];
    const float* lnw    = (const float*)d_in[5];
    const float* lnb    = (const float*)d_in[6];
    float* out = (float*)d_out;

    k_front<<<512, 256>>>(values, query, keys);
    k_M<<<64, 256>>>(W);
    k_compute<<<512, 256>>>(b, lnw, lnb, out);
    k_bcast<<<256, 256>>>(out);
}

// round 15
// speedup vs baseline: 1.0620x; 1.0620x over previous
#include <cuda_runtime.h>

#define NB 64
#define LQ 256
#define EE 64
#define HH 64

// Scratch (static __device__ — no allocations allowed)
__device__ float g_vt[NB * LQ * EE];    // vt[n][l][k] = values[k][l][n]   (4 MB)
__device__ float g_attn[NB * EE * EE];  // attn[n][a][b]                   (1 MB)

// ---------------------------------------------------------------------------
// K_front: merged launch (EXACT R10 structure — 4 experiments confirmed best).
//   blocks [0,128):   energy Q·K^T + softmax -> g_attn  (n, half)
//   blocks [128,384): transpose values[k][l][n] -> vt[n][l][k]  (one per l)
// ---------------------------------------------------------------------------
__global__ void __launch_bounds__(256) k_front(const float* __restrict__ values,
                                               const float* __restrict__ query,
                                               const float* __restrict__ keys) {
    __shared__ float sh[5248];           // aliased pool (max of both phases)
    const int tid = threadIdx.x;

    if (blockIdx.x >= 128) {
        // ---- transpose phase ----
        float (*tile)[65] = (float(*)[65])sh;
        const int l = blockIdx.x - 128;
#pragma unroll
        for (int i = 0; i < 4; i++) {
            int f = i * 256 + tid;          // float4 index 0..1023
            int k = f >> 4;                 // 0..63
            int n4 = f & 15;                // 0..15
            float4 v = *(const float4*)(values + ((k * LQ + l) * EE) + n4 * 4);
            tile[k][n4 * 4 + 0] = v.x;
            tile[k][n4 * 4 + 1] = v.y;
            tile[k][n4 * 4 + 2] = v.z;
            tile[k][n4 * 4 + 3] = v.w;
        }
        __syncthreads();
#pragma unroll
        for (int i = 0; i < 4; i++) {
            int f = i * 256 + tid;
            int nn = f >> 4;
            int k4 = f & 15;
            float4 v = make_float4(tile[k4 * 4 + 0][nn], tile[k4 * 4 + 1][nn],
                                   tile[k4 * 4 + 2][nn], tile[k4 * 4 + 3][nn]);
            *(float4*)(g_vt + ((nn * LQ + l) * EE) + k4 * 4) = v;
        }
        return;
    }

    // ---- attention phase ----
    const int n = blockIdx.x >> 1;
    const int half = blockIdx.x & 1;
    float (*sQ)[32] = (float(*)[32])sh;            // [l'][a_local]  1024
    float (*sK)[64] = (float(*)[64])(sh + 1024);   // [l'][b]        2048
    float (*sE)[68] = (float(*)[68])(sh + 3072);   // energy         2176
    const int a0 = (tid >> 4) * 2;  // 0..30 step 2
    const int b0 = (tid & 15) * 4;  // 0..60 step 4

    // per-thread load slots
    const int qlp = tid >> 3;        // 0..31 (Q row)
    const int qc = (tid & 7) * 4;    // 0..28 (Q col*4)
    const int klp0 = tid >> 4;       // 0..15 (K rows: tid and tid+256)
    const int kc = (tid & 15) * 4;   // 0..60

    float a00 = 0.f, a01 = 0.f, a02 = 0.f, a03 = 0.f;
    float a10 = 0.f, a11 = 0.f, a12 = 0.f, a13 = 0.f;

    // prefetch chunk 0
    float4 qreg = *(const float4*)(query + ((n * LQ + qlp) * EE) + half * 32 + qc);
    float4 kreg0 = *(const float4*)(keys + ((n * LQ + klp0) * EE) + kc);
    float4 kreg1 = *(const float4*)(keys + ((n * LQ + 16 + klp0) * EE) + kc);

    for (int c = 0; c < 8; c++) {
        *(float4*)&sQ[qlp][qc] = qreg;
        *(float4*)&sK[klp0][kc] = kreg0;
        *(float4*)&sK[16 + klp0][kc] = kreg1;
        __syncthreads();

        if (c < 7) {
            const int l0 = (c + 1) * 32;
            qreg = *(const float4*)(query + ((n * LQ + l0 + qlp) * EE) + half * 32 + qc);
            kreg0 = *(const float4*)(keys + ((n * LQ + l0 + klp0) * EE) + kc);
            kreg1 = *(const float4*)(keys + ((n * LQ + l0 + 16 + klp0) * EE) + kc);
        }

#pragma unroll
        for (int lp = 0; lp < 32; lp++) {
            float2 qv = *(const float2*)&sQ[lp][a0];
            float4 kv = *(const float4*)&sK[lp][b0];
            a00 += qv.x * kv.x; a01 += qv.x * kv.y; a02 += qv.x * kv.z; a03 += qv.x * kv.w;
            a10 += qv.y * kv.x; a11 += qv.y * kv.y; a12 += qv.y * kv.z; a13 += qv.y * kv.w;
        }
        __syncthreads();
    }
    *(float4*)&sE[a0][b0]     = make_float4(a00, a01, a02, a03);
    *(float4*)&sE[a0 + 1][b0] = make_float4(a10, a11, a12, a13);
    __syncthreads();

    // softmax: 8 warps x 4 rows each (32 rows in this half); hd=1 so no scale
    const int w = tid >> 5, lane = tid & 31;
#pragma unroll
    for (int r = 0; r < 4; r++) {
        int row = w * 4 + r;
        float v0 = sE[row][lane];
        float v1 = sE[row][lane + 32];
        float m = fmaxf(v0, v1);
#pragma unroll
        for (int off = 16; off; off >>= 1) m = fmaxf(m, __shfl_xor_sync(0xffffffffu, m, off));
        float e0 = __expf(v0 - m);
        float e1 = __expf(v1 - m);
        float s = e0 + e1;
#pragma unroll
        for (int off = 16; off; off >>= 1) s += __shfl_xor_sync(0xffffffffu, s, off);
        float inv = 1.0f / s;
        float* dst = g_attn + (n * EE + half * 32 + row) * EE;
        dst[lane] = e0 * inv;
        dst[lane + 32] = e1 * inv;
    }
}

// ---------------------------------------------------------------------------
// K3: reassociated  f = W @ (A_n @ vt^T)  + LayerNorm; h=0 slice only.
//   phase 1: g[l,e'] = sum_k A_n[e',k] * vt[l,k]
//   phase 2: f[l,e]  = b[e] + sum_e' W[e,e'] * g[l,e']  -> LN -> out
// Eliminates the k_M launch + g_M round-trip. 53 KB smem -> 4 CTAs/SM.
// grid: 512 blocks = (n, 32-l chunk); 256 threads.
// ---------------------------------------------------------------------------
__global__ void __launch_bounds__(256) k_compute(const float* __restrict__ W,
                                                 const float* __restrict__ bias,
                                                 const float* __restrict__ lnw,
                                                 const float* __restrict__ lnb,
                                                 float* __restrict__ out) {
    const int n = blockIdx.x >> 3;
    const int lc = blockIdx.x & 7;
    const int tid = threadIdx.x;

    __shared__ float sAt[64][68];   // [k][e'] = A_n[e'][k]
    __shared__ float sWt[64][68];   // [e'][e] = W[e][e']
    __shared__ float sv[32][68];    // [l'][k] vt tile; sy aliases after phase 1
    __shared__ float sg[32][68];    // [l'][e'] intermediate g
    __shared__ float sb[64], sw[64], sbeta[64];

    if (tid < 64) {
        sb[tid] = bias[tid];
        sw[tid] = lnw[tid];
        sbeta[tid] = lnb[tid];
    }

    // stage A_n transposed and W transposed (coalesced gmem reads)
    const float* An = g_attn + n * 4096;
#pragma unroll
    for (int i = 0; i < 16; i++) {
        int idx = i * 256 + tid;
        int r = idx >> 6, c = idx & 63;
        sAt[c][r] = An[idx];           // sAt[k][e'] = A[e'][k]
        sWt[c][r] = W[idx];            // sWt[e'][e] = W[e][e']
    }
    // vt tile (32 x 64), coalesced
    const int lbase = lc * 32;
    const float* vtn = g_vt + (n * LQ + lbase) * EE;
#pragma unroll
    for (int i = 0; i < 8; i++) {
        int idx = i * 256 + tid;
        sv[idx >> 6][idx & 63] = vtn[idx];
    }
    __syncthreads();

    const int r0 = (tid >> 4) * 2;   // l rows 0..30
    const int e0 = (tid & 15) * 4;   // col quad 0..60

    // ---- phase 1: g[l][e'] = sum_k vt[l][k] * A[e'][k] ----
    {
        float g00 = 0.f, g01 = 0.f, g02 = 0.f, g03 = 0.f;
        float g10 = 0.f, g11 = 0.f, g12 = 0.f, g13 = 0.f;
#pragma unroll
        for (int k = 0; k < 64; k++) {
            float v0 = sv[r0][k];
            float v1 = sv[r0 + 1][k];
            float4 a = *(const float4*)&sAt[k][e0];
            g00 += v0 * a.x; g01 += v0 * a.y; g02 += v0 * a.z; g03 += v0 * a.w;
            g10 += v1 * a.x; g11 += v1 * a.y; g12 += v1 * a.z; g13 += v1 * a.w;
        }
        *(float4*)&sg[r0][e0]     = make_float4(g00, g01, g02, g03);
        *(float4*)&sg[r0 + 1][e0] = make_float4(g10, g11, g12, g13);
    }
    __syncthreads();

    // ---- phase 2: f[l][e] = b[e] + sum_e' g[l][e'] * W[e][e'] ----
    float a00 = 0.f, a01 = 0.f, a02 = 0.f, a03 = 0.f;
    float a10 = 0.f, a11 = 0.f, a12 = 0.f, a13 = 0.f;
#pragma unroll
    for (int ep = 0; ep < 64; ep++) {
        float v0 = sg[r0][ep];
        float v1 = sg[r0 + 1][ep];
        float4 m = *(const float4*)&sWt[ep][e0];
        a00 += v0 * m.x; a01 += v0 * m.y; a02 += v0 * m.z; a03 += v0 * m.w;
        a10 += v1 * m.x; a11 += v1 * m.y; a12 += v1 * m.z; a13 += v1 * m.w;
    }
    float b0v = sb[e0], b1v = sb[e0 + 1], b2v = sb[e0 + 2], b3v = sb[e0 + 3];
    a00 += b0v; a01 += b1v; a02 += b2v; a03 += b3v;
    a10 += b0v; a11 += b1v; a12 += b2v; a13 += b3v;

    // LN stats: reduce over the 16 lanes sharing a row-pair (offsets 1..8)
    float s0 = (a00 + a01) + (a02 + a03);
    float q0 = (a00 * a00 + a01 * a01) + (a02 * a02 + a03 * a03);
    float s1 = (a10 + a11) + (a12 + a13);
    float q1 = (a10 * a10 + a11 * a11) + (a12 * a12 + a13 * a13);
#pragma unroll
    for (int off = 8; off; off >>= 1) {
        s0 += __shfl_xor_sync(0xffffffffu, s0, off);
        q0 += __shfl_xor_sync(0xffffffffu, q0, off);
        s1 += __shfl_xor_sync(0xffffffffu, s1, off);
        q1 += __shfl_xor_sync(0xffffffffu, q1, off);
    }
    float mu0 = s0 * (1.0f / 64.0f);
    float var0 = q0 * (1.0f / 64.0f) - mu0 * mu0;
    float ri0 = rsqrtf(var0 + 1e-5f);
    float mu1 = s1 * (1.0f / 64.0f);
    float var1 = q1 * (1.0f / 64.0f) - mu1 * mu1;
    float ri1 = rsqrtf(var1 + 1e-5f);

    float w0 = sw[e0], w1 = sw[e0 + 1], w2 = sw[e0 + 2], w3 = sw[e0 + 3];
    float g0 = sbeta[e0], g1 = sbeta[e0 + 1], g2 = sbeta[e0 + 2], g3 = sbeta[e0 + 3];

    // sy aliases sv (all sv reads completed before the phase-1 sync)
    float (*sy)[68] = sv;
    *(float4*)&sy[r0][e0] = make_float4((a00 - mu0) * ri0 * w0 + g0,
                                        (a01 - mu0) * ri0 * w1 + g1,
                                        (a02 - mu0) * ri0 * w2 + g2,
                                        (a03 - mu0) * ri0 * w3 + g3);
    *(float4*)&sy[r0 + 1][e0] = make_float4((a10 - mu1) * ri1 * w0 + g0,
                                            (a11 - mu1) * ri1 * w1 + g1,
                                            (a12 - mu1) * ri1 * w2 + g2,
                                            (a13 - mu1) * ri1 * w3 + g3);
    __syncthreads();

    // write h = 0 slice only (coalesced STG.128); sy rows are 68-float padded
    {
        int row = tid >> 3;          // 0..31
        int c4 = (tid & 7) * 2;      // float4 pairs: cols 0..14 step 2
        float4* dst = (float4*)out + n * 4096 + (lbase + row) * 16 + c4;
        const float4* srow = (const float4*)&sy[row][0];
        dst[0] = srow[c4];
        dst[1] = srow[c4 + 1];
    }
}

// ---------------------------------------------------------------------------
// K4: broadcast h=0 slice to h = 1..63. NEW: register-resident source AND
// fully contiguous per-block writes. grid 4032 = (h-1)*64 + seg: block loads
// its 64 KB segment once (16 LDG.128/thread, L2-hot) then writes one
// contiguous 64 KB run (16 independent STG.128/thread).
// ---------------------------------------------------------------------------
__global__ void __launch_bounds__(256) k_bcast(float* __restrict__ out) {
    const int tid = threadIdx.x;
    const int h = (int)(blockIdx.x >> 6) + 1;     // 1..63
    const int seg = blockIdx.x & 63;              // 0..63 (64 KB each)
    const float4* src = (const float4*)out + (size_t)seg * 4096;
    float4 v[16];
#pragma unroll
    for (int i = 0; i < 16; i++) v[i] = src[i * 256 + tid];
    float4* dst = (float4*)out + (size_t)h * 262144 + (size_t)seg * 4096 + tid;
#pragma unroll
    for (int i = 0; i < 16; i++) dst[i * 256] = v[i];
}

// ---------------------------------------------------------------------------
extern "C" void kernel_launch(void* const* d_in, const int* in_sizes, int n_in,
                              void* d_out, int out_size) {
    const float* values = (const float*)d_in[0];
    const float* keys   = (const float*)d_in[1];
    const float* query  = (const float*)d_in[2];
    const float* W      = (const float*)d_in[3];
    const float* b      = (const float*)d_in[4];
    const float* lnw    = (const float*)d_in[5];
    const float* lnb    = (const float*)d_in[6];
    float* out = (float*)d_out;

    k_front<<<384, 256>>>(values, query, keys);
    k_compute<<<512, 256>>>(W, b, lnw, lnb, out);
    k_bcast<<<4032, 256>>>(out);
}

// round 16
// speedup vs baseline: 1.1214x; 1.0559x over previous
#include <cuda_runtime.h>

#define NB 64
#define LQ 256
#define EE 64
#define HH 64

// Scratch (static __device__ — no allocations allowed)
__device__ float g_vt[NB * LQ * EE];    // vt[n][l][k] = values[k][l][n]   (4 MB)
__device__ float g_attn[NB * EE * EE];  // attn[n][a][b]                   (1 MB)

// ---------------------------------------------------------------------------
// K_front: merged launch, 256 blocks x 512 threads.
//   blocks [0,128):   attn (n, half): split-l — group 0 (tid<256) sums
//                     l in [0,128), group 1 sums [128,256); partials combined
//                     in smem, then softmax -> g_attn.
//   blocks [128,256): transpose: 2 l-values per block (one per group).
// ---------------------------------------------------------------------------
__global__ void __launch_bounds__(512) k_front(const float* __restrict__ values,
                                               const float* __restrict__ query,
                                               const float* __restrict__ keys) {
    __shared__ float sh[10496];          // 42 KB aliased pool
    const int tid = threadIdx.x;
    const int g = tid >> 8;              // l-group 0/1
    const int t = tid & 255;

    if (blockIdx.x >= 128) {
        // ---- transpose phase: l = 2*(b-128) + g ----
        float (*tile)[65] = (float(*)[65])(sh + g * 4160);
        const int l = ((blockIdx.x - 128) << 1) + g;
#pragma unroll
        for (int i = 0; i < 4; i++) {
            int f = i * 256 + t;            // float4 index 0..1023
            int k = f >> 4;                 // 0..63
            int n4 = f & 15;                // 0..15
            float4 v = *(const float4*)(values + ((k * LQ + l) * EE) + n4 * 4);
            tile[k][n4 * 4 + 0] = v.x;
            tile[k][n4 * 4 + 1] = v.y;
            tile[k][n4 * 4 + 2] = v.z;
            tile[k][n4 * 4 + 3] = v.w;
        }
        __syncthreads();
#pragma unroll
        for (int i = 0; i < 4; i++) {
            int f = i * 256 + t;
            int nn = f >> 4;
            int k4 = f & 15;
            float4 v = make_float4(tile[k4 * 4 + 0][nn], tile[k4 * 4 + 1][nn],
                                   tile[k4 * 4 + 2][nn], tile[k4 * 4 + 3][nn]);
            *(float4*)(g_vt + ((nn * LQ + l) * EE) + k4 * 4) = v;
        }
        return;
    }

    // ---- attention phase ----
    const int n = blockIdx.x >> 1;
    const int half = blockIdx.x & 1;
    float (*sQ)[32] = (float(*)[32])(sh + g * 1024);          // [l'][a_local]
    float (*sK)[64] = (float(*)[64])(sh + 2048 + g * 2048);   // [l'][b]
    float (*sE0)[68] = (float(*)[68])(sh + 6144);             // partial E, grp 0
    float (*sE1)[68] = (float(*)[68])(sh + 6144 + 2176);      // partial E, grp 1
    float (*sEg)[68] = g ? sE1 : sE0;

    const int a0 = (t >> 4) * 2;     // 0..30 step 2
    const int b0 = (t & 15) * 4;     // 0..60 step 4

    // per-thread load slots (within this group's 128-l range)
    const int qlp = t >> 3;          // 0..31 (Q row)
    const int qc = (t & 7) * 4;      // 0..28 (Q col*4)
    const int klp0 = t >> 4;         // 0..15 (K rows: klp0 and klp0+16)
    const int kc = (t & 15) * 4;     // 0..60

    const float* qb = query + ((size_t)n * LQ + g * 128) * EE + half * 32;
    const float* kb = keys + ((size_t)n * LQ + g * 128) * EE;

    float a00 = 0.f, a01 = 0.f, a02 = 0.f, a03 = 0.f;
    float a10 = 0.f, a11 = 0.f, a12 = 0.f, a13 = 0.f;

    // prefetch chunk 0
    float4 qreg = *(const float4*)(qb + qlp * EE + qc);
    float4 kreg0 = *(const float4*)(kb + klp0 * EE + kc);
    float4 kreg1 = *(const float4*)(kb + (16 + klp0) * EE + kc);

    for (int c = 0; c < 4; c++) {
        *(float4*)&sQ[qlp][qc] = qreg;
        *(float4*)&sK[klp0][kc] = kreg0;
        *(float4*)&sK[16 + klp0][kc] = kreg1;
        __syncthreads();

        if (c < 3) {
            const int l0 = (c + 1) * 32;
            qreg = *(const float4*)(qb + (l0 + qlp) * EE + qc);
            kreg0 = *(const float4*)(kb + (l0 + klp0) * EE + kc);
            kreg1 = *(const float4*)(kb + (l0 + 16 + klp0) * EE + kc);
        }

#pragma unroll
        for (int lp = 0; lp < 32; lp++) {
            float2 qv = *(const float2*)&sQ[lp][a0];
            float4 kv = *(const float4*)&sK[lp][b0];
            a00 += qv.x * kv.x; a01 += qv.x * kv.y; a02 += qv.x * kv.z; a03 += qv.x * kv.w;
            a10 += qv.y * kv.x; a11 += qv.y * kv.y; a12 += qv.y * kv.z; a13 += qv.y * kv.w;
        }
        __syncthreads();
    }
    *(float4*)&sEg[a0][b0]     = make_float4(a00, a01, a02, a03);
    *(float4*)&sEg[a0 + 1][b0] = make_float4(a10, a11, a12, a13);
    __syncthreads();

    // softmax: 16 warps x 2 rows each (32 rows in this half); hd=1 no scale
    const int w = tid >> 5, lane = tid & 31;
#pragma unroll
    for (int r = 0; r < 2; r++) {
        int row = w * 2 + r;
        float v0 = sE0[row][lane] + sE1[row][lane];
        float v1 = sE0[row][lane + 32] + sE1[row][lane + 32];
        float m = fmaxf(v0, v1);
#pragma unroll
        for (int off = 16; off; off >>= 1) m = fmaxf(m, __shfl_xor_sync(0xffffffffu, m, off));
        float e0 = __expf(v0 - m);
        float e1 = __expf(v1 - m);
        float s = e0 + e1;
#pragma unroll
        for (int off = 16; off; off >>= 1) s += __shfl_xor_sync(0xffffffffu, s, off);
        float inv = 1.0f / s;
        float* dst = g_attn + (n * EE + half * 32 + row) * EE;
        dst[lane] = e0 * inv;
        dst[lane + 32] = e1 * inv;
    }
}

// ---------------------------------------------------------------------------
// K3: reassociated  f = W @ (A_n @ vt^T)  + LayerNorm; h=0 slice only.
//   phase 1: g[l,e'] = sum_k A_n[e',k] * vt[l,k]
//   phase 2: f[l,e]  = b[e] + sum_e' W[e,e'] * g[l,e']  -> LN -> out
// grid: 512 blocks = (n, 32-l chunk); 256 threads.
// ---------------------------------------------------------------------------
__global__ void __launch_bounds__(256) k_compute(const float* __restrict__ W,
                                                 const float* __restrict__ bias,
                                                 const float* __restrict__ lnw,
                                                 const float* __restrict__ lnb,
                                                 float* __restrict__ out) {
    const int n = blockIdx.x >> 3;
    const int lc = blockIdx.x & 7;
    const int tid = threadIdx.x;

    __shared__ float sAt[64][68];   // [k][e'] = A_n[e'][k]
    __shared__ float sWt[64][68];   // [e'][e] = W[e][e']
    __shared__ float sv[32][68];    // [l'][k] vt tile; sy aliases after phase 1
    __shared__ float sg[32][68];    // [l'][e'] intermediate g
    __shared__ float sb[64], sw[64], sbeta[64];

    if (tid < 64) {
        sb[tid] = bias[tid];
        sw[tid] = lnw[tid];
        sbeta[tid] = lnb[tid];
    }

    // stage A_n transposed and W transposed (coalesced gmem reads)
    const float* An = g_attn + n * 4096;
#pragma unroll
    for (int i = 0; i < 16; i++) {
        int idx = i * 256 + tid;
        int r = idx >> 6, c = idx & 63;
        sAt[c][r] = An[idx];           // sAt[k][e'] = A[e'][k]
        sWt[c][r] = W[idx];            // sWt[e'][e] = W[e][e']
    }
    // vt tile (32 x 64), coalesced
    const int lbase = lc * 32;
    const float* vtn = g_vt + (n * LQ + lbase) * EE;
#pragma unroll
    for (int i = 0; i < 8; i++) {
        int idx = i * 256 + tid;
        sv[idx >> 6][idx & 63] = vtn[idx];
    }
    __syncthreads();

    const int r0 = (tid >> 4) * 2;   // l rows 0..30
    const int e0 = (tid & 15) * 4;   // col quad 0..60

    // ---- phase 1: g[l][e'] = sum_k vt[l][k] * A[e'][k] ----
    {
        float g00 = 0.f, g01 = 0.f, g02 = 0.f, g03 = 0.f;
        float g10 = 0.f, g11 = 0.f, g12 = 0.f, g13 = 0.f;
#pragma unroll
        for (int k = 0; k < 64; k++) {
            float v0 = sv[r0][k];
            float v1 = sv[r0 + 1][k];
            float4 a = *(const float4*)&sAt[k][e0];
            g00 += v0 * a.x; g01 += v0 * a.y; g02 += v0 * a.z; g03 += v0 * a.w;
            g10 += v1 * a.x; g11 += v1 * a.y; g12 += v1 * a.z; g13 += v1 * a.w;
        }
        *(float4*)&sg[r0][e0]     = make_float4(g00, g01, g02, g03);
        *(float4*)&sg[r0 + 1][e0] = make_float4(g10, g11, g12, g13);
    }
    __syncthreads();

    // ---- phase 2: f[l][e] = b[e] + sum_e' g[l][e'] * W[e][e'] ----
    float a00 = 0.f, a01 = 0.f, a02 = 0.f, a03 = 0.f;
    float a10 = 0.f, a11 = 0.f, a12 = 0.f, a13 = 0.f;
#pragma unroll
    for (int ep = 0; ep < 64; ep++) {
        float v0 = sg[r0][ep];
        float v1 = sg[r0 + 1][ep];
        float4 m = *(const float4*)&sWt[ep][e0];
        a00 += v0 * m.x; a01 += v0 * m.y; a02 += v0 * m.z; a03 += v0 * m.w;
        a10 += v1 * m.x; a11 += v1 * m.y; a12 += v1 * m.z; a13 += v1 * m.w;
    }
    float b0v = sb[e0], b1v = sb[e0 + 1], b2v = sb[e0 + 2], b3v = sb[e0 + 3];
    a00 += b0v; a01 += b1v; a02 += b2v; a03 += b3v;
    a10 += b0v; a11 += b1v; a12 += b2v; a13 += b3v;

    // LN stats: reduce over the 16 lanes sharing a row-pair (offsets 1..8)
    float s0 = (a00 + a01) + (a02 + a03);
    float q0 = (a00 * a00 + a01 * a01) + (a02 * a02 + a03 * a03);
    float s1 = (a10 + a11) + (a12 + a13);
    float q1 = (a10 * a10 + a11 * a11) + (a12 * a12 + a13 * a13);
#pragma unroll
    for (int off = 8; off; off >>= 1) {
        s0 += __shfl_xor_sync(0xffffffffu, s0, off);
        q0 += __shfl_xor_sync(0xffffffffu, q0, off);
        s1 += __shfl_xor_sync(0xffffffffu, s1, off);
        q1 += __shfl_xor_sync(0xffffffffu, q1, off);
    }
    float mu0 = s0 * (1.0f / 64.0f);
    float var0 = q0 * (1.0f / 64.0f) - mu0 * mu0;
    float ri0 = rsqrtf(var0 + 1e-5f);
    float mu1 = s1 * (1.0f / 64.0f);
    float var1 = q1 * (1.0f / 64.0f) - mu1 * mu1;
    float ri1 = rsqrtf(var1 + 1e-5f);

    float w0 = sw[e0], w1 = sw[e0 + 1], w2 = sw[e0 + 2], w3 = sw[e0 + 3];
    float g0 = sbeta[e0], g1 = sbeta[e0 + 1], g2 = sbeta[e0 + 2], g3 = sbeta[e0 + 3];

    // sy aliases sv (all sv reads completed before the phase-1 sync)
    float (*sy)[68] = sv;
    *(float4*)&sy[r0][e0] = make_float4((a00 - mu0) * ri0 * w0 + g0,
                                        (a01 - mu0) * ri0 * w1 + g1,
                                        (a02 - mu0) * ri0 * w2 + g2,
                                        (a03 - mu0) * ri0 * w3 + g3);
    *(float4*)&sy[r0 + 1][e0] = make_float4((a10 - mu1) * ri1 * w0 + g0,
                                            (a11 - mu1) * ri1 * w1 + g1,
                                            (a12 - mu1) * ri1 * w2 + g2,
                                            (a13 - mu1) * ri1 * w3 + g3);
    __syncthreads();

    // write h = 0 slice only (coalesced STG.128); sy rows are 68-float padded
    {
        int row = tid >> 3;          // 0..31
        int c4 = (tid & 7) * 2;      // float4 pairs: cols 0..14 step 2
        float4* dst = (float4*)out + n * 4096 + (lbase + row) * 16 + c4;
        const float4* srow = (const float4*)&sy[row][0];
        dst[0] = srow[c4];
        dst[1] = srow[c4 + 1];
    }
}

// ---------------------------------------------------------------------------
// K4: broadcast h=0 slice to h = 1..63. Register-resident source + contiguous
// per-block writes: grid 4032 = (h-1)*64 + seg; block loads its 64 KB segment
// (16 LDG.128/thread, L2-hot), writes one contiguous 64 KB run.
// ---------------------------------------------------------------------------
__global__ void __launch_bounds__(256) k_bcast(float* __restrict__ out) {
    const int tid = threadIdx.x;
    const int h = (int)(blockIdx.x >> 6) + 1;     // 1..63
    const int seg = blockIdx.x & 63;              // 0..63 (64 KB each)
    const float4* src = (const float4*)out + (size_t)seg * 4096;
    float4 v[16];
#pragma unroll
    for (int i = 0; i < 16; i++) v[i] = src[i * 256 + tid];
    float4* dst = (float4*)out + (size_t)h * 262144 + (size_t)seg * 4096 + tid;
#pragma unroll
    for (int i = 0; i < 16; i++) dst[i * 256] = v[i];
}

// ---------------------------------------------------------------------------
extern "C" void kernel_launch(void* const* d_in, const int* in_sizes, int n_in,
                              void* d_out, int out_size) {
    const float* values = (const float*)d_in[0];
    const float* keys   = (const float*)d_in[1];
    const float* query  = (const float*)d_in[2];
    const float* W      = (const float*)d_in[3];
    const float* b      = (const float*)d_in[4];
    const float* lnw    = (const float*)d_in[5];
    const float* lnb    = (const float*)d_in[6];
    float* out = (float*)d_out;

    k_front<<<256, 512>>>(values, query, keys);
    k_compute<<<512, 256>>>(W, b, lnw, lnb, out);
    k_bcast<<<4032, 256>>>(out);
}

// round 17
// speedup vs baseline: 1.1515x; 1.0268x over previous
#include <cuda_runtime.h>

#define NB 64
#define LQ 256
#define EE 64
#define HH 64

// Scratch (static __device__ — no allocations allowed)
__device__ float g_vt[NB * LQ * EE];    // vt[n][l][k] = values[k][l][n]   (4 MB)
__device__ float g_attn[NB * EE * EE];  // attn[n][a][b]                   (1 MB)

// ---------------------------------------------------------------------------
// K_front: merged launch, 256 blocks x 512 threads, 88 KB dynamic smem.
//   blocks [0,128):   attn (n, half): 4 l-groups of 128 threads; group g sums
//                     l in [g*64, g*64+64) with 4a x 4b register tiles;
//                     4 partial-E buffers combined in softmax -> g_attn.
//   blocks [128,256): transpose: 2 l-values per block (tid>>8 selects).
// Smem pool (floats): sQ[g] at g*1152 ([32][36]); sK[g] at 4608+g*2176
// ([32][68]); sE[g] at 13312+g*2176 ([32][68]). Total 22016 floats.
// ---------------------------------------------------------------------------
__global__ void __launch_bounds__(512) k_front(const float* __restrict__ values,
                                               const float* __restrict__ query,
                                               const float* __restrict__ keys) {
    extern __shared__ float sh[];
    const int tid = threadIdx.x;

    if (blockIdx.x >= 128) {
        // ---- transpose phase: l = 2*(b-128) + (tid>>8) ----
        const int gt = tid >> 8;
        const int t = tid & 255;
        float (*tile)[65] = (float(*)[65])(sh + gt * 4160);
        const int l = ((blockIdx.x - 128) << 1) + gt;
#pragma unroll
        for (int i = 0; i < 4; i++) {
            int f = i * 256 + t;            // float4 index 0..1023
            int k = f >> 4;                 // 0..63
            int n4 = f & 15;                // 0..15
            float4 v = *(const float4*)(values + ((k * LQ + l) * EE) + n4 * 4);
            tile[k][n4 * 4 + 0] = v.x;
            tile[k][n4 * 4 + 1] = v.y;
            tile[k][n4 * 4 + 2] = v.z;
            tile[k][n4 * 4 + 3] = v.w;
        }
        __syncthreads();
#pragma unroll
        for (int i = 0; i < 4; i++) {
            int f = i * 256 + t;
            int nn = f >> 4;
            int k4 = f & 15;
            float4 v = make_float4(tile[k4 * 4 + 0][nn], tile[k4 * 4 + 1][nn],
                                   tile[k4 * 4 + 2][nn], tile[k4 * 4 + 3][nn]);
            *(float4*)(g_vt + ((nn * LQ + l) * EE) + k4 * 4) = v;
        }
        return;
    }

    // ---- attention phase ----
    const int n = blockIdx.x >> 1;
    const int half = blockIdx.x & 1;
    const int g = tid >> 7;              // l-group 0..3
    const int t = tid & 127;

    float (*sQ)[36] = (float(*)[36])(sh + g * 1152);           // [l'][a_local]
    float (*sK)[68] = (float(*)[68])(sh + 4608 + g * 2176);    // [l'][b]
    float* sEbase = sh + 13312;                                // 4 partials

    const int a0 = (t >> 4) * 4;     // 0..28 step 4 (a_local)
    const int b0 = (t & 15) * 4;     // 0..60 step 4

    const float* qb = query + ((size_t)n * LQ + g * 64) * EE + half * 32;
    const float* kb = keys + ((size_t)n * LQ + g * 64) * EE;

    float acc[4][4] = {};

    // prefetch chunk 0 (per-thread: 2 Q quads, 4 K quads)
    float4 qr0, qr1, kr0, kr1, kr2, kr3;
    {
        int i0 = t, i1 = t + 128;                 // Q quad slots (256 total)
        qr0 = *(const float4*)(qb + (i0 >> 3) * EE + (i0 & 7) * 4);
        qr1 = *(const float4*)(qb + (i1 >> 3) * EE + (i1 & 7) * 4);
        kr0 = *(const float4*)(kb + (t >> 4) * EE + (t & 15) * 4);
        kr1 = *(const float4*)(kb + ((t + 128) >> 4) * EE + (t & 15) * 4);
        kr2 = *(const float4*)(kb + ((t + 256) >> 4) * EE + (t & 15) * 4);
        kr3 = *(const float4*)(kb + ((t + 384) >> 4) * EE + (t & 15) * 4);
    }

    for (int c = 0; c < 2; c++) {
        {
            int i0 = t, i1 = t + 128;
            *(float4*)&sQ[i0 >> 3][(i0 & 7) * 4] = qr0;
            *(float4*)&sQ[i1 >> 3][(i1 & 7) * 4] = qr1;
            *(float4*)&sK[t >> 4][(t & 15) * 4] = kr0;
            *(float4*)&sK[(t + 128) >> 4][(t & 15) * 4] = kr1;
            *(float4*)&sK[(t + 256) >> 4][(t & 15) * 4] = kr2;
            *(float4*)&sK[(t + 384) >> 4][(t & 15) * 4] = kr3;
        }
        __syncthreads();

        if (c == 0) {
            const float* qb2 = qb + 32 * EE;
            const float* kb2 = kb + 32 * EE;
            int i0 = t, i1 = t + 128;
            qr0 = *(const float4*)(qb2 + (i0 >> 3) * EE + (i0 & 7) * 4);
            qr1 = *(const float4*)(qb2 + (i1 >> 3) * EE + (i1 & 7) * 4);
            kr0 = *(const float4*)(kb2 + (t >> 4) * EE + (t & 15) * 4);
            kr1 = *(const float4*)(kb2 + ((t + 128) >> 4) * EE + (t & 15) * 4);
            kr2 = *(const float4*)(kb2 + ((t + 256) >> 4) * EE + (t & 15) * 4);
            kr3 = *(const float4*)(kb2 + ((t + 384) >> 4) * EE + (t & 15) * 4);
        }

#pragma unroll
        for (int lp = 0; lp < 32; lp++) {
            float4 qv = *(const float4*)&sQ[lp][a0];
            float4 kv = *(const float4*)&sK[lp][b0];
            acc[0][0] += qv.x * kv.x; acc[0][1] += qv.x * kv.y; acc[0][2] += qv.x * kv.z; acc[0][3] += qv.x * kv.w;
            acc[1][0] += qv.y * kv.x; acc[1][1] += qv.y * kv.y; acc[1][2] += qv.y * kv.z; acc[1][3] += qv.y * kv.w;
            acc[2][0] += qv.z * kv.x; acc[2][1] += qv.z * kv.y; acc[2][2] += qv.z * kv.z; acc[2][3] += qv.z * kv.w;
            acc[3][0] += qv.w * kv.x; acc[3][1] += qv.w * kv.y; acc[3][2] += qv.w * kv.z; acc[3][3] += qv.w * kv.w;
        }
        __syncthreads();
    }

    // store this group's partial energy
    {
        float (*sEg)[68] = (float(*)[68])(sEbase + g * 2176);
#pragma unroll
        for (int i = 0; i < 4; i++)
            *(float4*)&sEg[a0 + i][b0] = make_float4(acc[i][0], acc[i][1], acc[i][2], acc[i][3]);
    }
    __syncthreads();

    // softmax: 16 warps x 2 rows (32 rows in this half); hd=1, no scale
    const int w = tid >> 5, lane = tid & 31;
    float (*sE0)[68] = (float(*)[68])(sEbase);
    float (*sE1)[68] = (float(*)[68])(sEbase + 2176);
    float (*sE2)[68] = (float(*)[68])(sEbase + 4352);
    float (*sE3)[68] = (float(*)[68])(sEbase + 6528);
#pragma unroll
    for (int r = 0; r < 2; r++) {
        int row = w * 2 + r;
        float v0 = (sE0[row][lane] + sE1[row][lane]) + (sE2[row][lane] + sE3[row][lane]);
        float v1 = (sE0[row][lane + 32] + sE1[row][lane + 32]) + (sE2[row][lane + 32] + sE3[row][lane + 32]);
        float m = fmaxf(v0, v1);
#pragma unroll
        for (int off = 16; off; off >>= 1) m = fmaxf(m, __shfl_xor_sync(0xffffffffu, m, off));
        float e0 = __expf(v0 - m);
        float e1 = __expf(v1 - m);
        float s = e0 + e1;
#pragma unroll
        for (int off = 16; off; off >>= 1) s += __shfl_xor_sync(0xffffffffu, s, off);
        float inv = 1.0f / s;
        float* dst = g_attn + (n * EE + half * 32 + row) * EE;
        dst[lane] = e0 * inv;
        dst[lane + 32] = e1 * inv;
    }
}

// ---------------------------------------------------------------------------
// K3: reassociated  f = W @ (A_n @ vt^T)  + LayerNorm; h=0 slice only.
// grid: 512 blocks = (n, 32-l chunk); 256 threads.  (identical to R16)
// ---------------------------------------------------------------------------
__global__ void __launch_bounds__(256) k_compute(const float* __restrict__ W,
                                                 const float* __restrict__ bias,
                                                 const float* __restrict__ lnw,
                                                 const float* __restrict__ lnb,
                                                 float* __restrict__ out) {
    const int n = blockIdx.x >> 3;
    const int lc = blockIdx.x & 7;
    const int tid = threadIdx.x;

    __shared__ float sAt[64][68];   // [k][e'] = A_n[e'][k]
    __shared__ float sWt[64][68];   // [e'][e] = W[e][e']
    __shared__ float sv[32][68];    // [l'][k] vt tile; sy aliases after phase 1
    __shared__ float sg[32][68];    // [l'][e'] intermediate g
    __shared__ float sb[64], sw[64], sbeta[64];

    if (tid < 64) {
        sb[tid] = bias[tid];
        sw[tid] = lnw[tid];
        sbeta[tid] = lnb[tid];
    }

    const float* An = g_attn + n * 4096;
#pragma unroll
    for (int i = 0; i < 16; i++) {
        int idx = i * 256 + tid;
        int r = idx >> 6, c = idx & 63;
        sAt[c][r] = An[idx];           // sAt[k][e'] = A[e'][k]
        sWt[c][r] = W[idx];            // sWt[e'][e] = W[e][e']
    }
    const int lbase = lc * 32;
    const float* vtn = g_vt + (n * LQ + lbase) * EE;
#pragma unroll
    for (int i = 0; i < 8; i++) {
        int idx = i * 256 + tid;
        sv[idx >> 6][idx & 63] = vtn[idx];
    }
    __syncthreads();

    const int r0 = (tid >> 4) * 2;   // l rows 0..30
    const int e0 = (tid & 15) * 4;   // col quad 0..60

    // ---- phase 1: g[l][e'] = sum_k vt[l][k] * A[e'][k] ----
    {
        float g00 = 0.f, g01 = 0.f, g02 = 0.f, g03 = 0.f;
        float g10 = 0.f, g11 = 0.f, g12 = 0.f, g13 = 0.f;
#pragma unroll
        for (int k = 0; k < 64; k++) {
            float v0 = sv[r0][k];
            float v1 = sv[r0 + 1][k];
            float4 a = *(const float4*)&sAt[k][e0];
            g00 += v0 * a.x; g01 += v0 * a.y; g02 += v0 * a.z; g03 += v0 * a.w;
            g10 += v1 * a.x; g11 += v1 * a.y; g12 += v1 * a.z; g13 += v1 * a.w;
        }
        *(float4*)&sg[r0][e0]     = make_float4(g00, g01, g02, g03);
        *(float4*)&sg[r0 + 1][e0] = make_float4(g10, g11, g12, g13);
    }
    __syncthreads();

    // ---- phase 2: f[l][e] = b[e] + sum_e' g[l][e'] * W[e][e'] ----
    float a00 = 0.f, a01 = 0.f, a02 = 0.f, a03 = 0.f;
    float a10 = 0.f, a11 = 0.f, a12 = 0.f, a13 = 0.f;
#pragma unroll
    for (int ep = 0; ep < 64; ep++) {
        float v0 = sg[r0][ep];
        float v1 = sg[r0 + 1][ep];
        float4 m = *(const float4*)&sWt[ep][e0];
        a00 += v0 * m.x; a01 += v0 * m.y; a02 += v0 * m.z; a03 += v0 * m.w;
        a10 += v1 * m.x; a11 += v1 * m.y; a12 += v1 * m.z; a13 += v1 * m.w;
    }
    float b0v = sb[e0], b1v = sb[e0 + 1], b2v = sb[e0 + 2], b3v = sb[e0 + 3];
    a00 += b0v; a01 += b1v; a02 += b2v; a03 += b3v;
    a10 += b0v; a11 += b1v; a12 += b2v; a13 += b3v;

    // LN stats: reduce over the 16 lanes sharing a row-pair (offsets 1..8)
    float s0 = (a00 + a01) + (a02 + a03);
    float q0 = (a00 * a00 + a01 * a01) + (a02 * a02 + a03 * a03);
    float s1 = (a10 + a11) + (a12 + a13);
    float q1 = (a10 * a10 + a11 * a11) + (a12 * a12 + a13 * a13);
#pragma unroll
    for (int off = 8; off; off >>= 1) {
        s0 += __shfl_xor_sync(0xffffffffu, s0, off);
        q0 += __shfl_xor_sync(0xffffffffu, q0, off);
        s1 += __shfl_xor_sync(0xffffffffu, s1, off);
        q1 += __shfl_xor_sync(0xffffffffu, q1, off);
    }
    float mu0 = s0 * (1.0f / 64.0f);
    float var0 = q0 * (1.0f / 64.0f) - mu0 * mu0;
    float ri0 = rsqrtf(var0 + 1e-5f);
    float mu1 = s1 * (1.0f / 64.0f);
    float var1 = q1 * (1.0f / 64.0f) - mu1 * mu1;
    float ri1 = rsqrtf(var1 + 1e-5f);

    float w0 = sw[e0], w1 = sw[e0 + 1], w2 = sw[e0 + 2], w3 = sw[e0 + 3];
    float g0 = sbeta[e0], g1 = sbeta[e0 + 1], g2 = sbeta[e0 + 2], g3 = sbeta[e0 + 3];

    float (*sy)[68] = sv;   // alias: all sv reads done before phase-1 sync
    *(float4*)&sy[r0][e0] = make_float4((a00 - mu0) * ri0 * w0 + g0,
                                        (a01 - mu0) * ri0 * w1 + g1,
                                        (a02 - mu0) * ri0 * w2 + g2,
                                        (a03 - mu0) * ri0 * w3 + g3);
    *(float4*)&sy[r0 + 1][e0] = make_float4((a10 - mu1) * ri1 * w0 + g0,
                                            (a11 - mu1) * ri1 * w1 + g1,
                                            (a12 - mu1) * ri1 * w2 + g2,
                                            (a13 - mu1) * ri1 * w3 + g3);
    __syncthreads();

    // write h = 0 slice only (coalesced STG.128); sy rows are 68-float padded
    {
        int row = tid >> 3;          // 0..31
        int c4 = (tid & 7) * 2;      // float4 pairs: cols 0..14 step 2
        float4* dst = (float4*)out + n * 4096 + (lbase + row) * 16 + c4;
        const float4* srow = (const float4*)&sy[row][0];
        dst[0] = srow[c4];
        dst[1] = srow[c4 + 1];
    }
}

// ---------------------------------------------------------------------------
// K4: broadcast h=0 slice to h = 1..63. Register-resident source + contiguous
// per-block writes: grid 4032 = (h-1)*64 + seg; block loads its 64 KB segment
// (16 LDG.128/thread, L2-hot), writes one contiguous 64 KB run. (R16 exact)
// ---------------------------------------------------------------------------
__global__ void __launch_bounds__(256) k_bcast(float* __restrict__ out) {
    const int tid = threadIdx.x;
    const int h = (int)(blockIdx.x >> 6) + 1;     // 1..63
    const int seg = blockIdx.x & 63;              // 0..63 (64 KB each)
    const float4* src = (const float4*)out + (size_t)seg * 4096;
    float4 v[16];
#pragma unroll
    for (int i = 0; i < 16; i++) v[i] = src[i * 256 + tid];
    float4* dst = (float4*)out + (size_t)h * 262144 + (size_t)seg * 4096 + tid;
#pragma unroll
    for (int i = 0; i < 16; i++) dst[i * 256] = v[i];
}

// ---------------------------------------------------------------------------
extern "C" void kernel_launch(void* const* d_in, const int* in_sizes, int n_in,
                              void* d_out, int out_size) {
    const float* values = (const float*)d_in[0];
    const float* keys   = (const float*)d_in[1];
    const float* query  = (const float*)d_in[2];
    const float* W      = (const float*)d_in[3];
    const float* b      = (const float*)d_in[4];
    const float* lnw    = (const float*)d_in[5];
    const float* lnb    = (const float*)d_in[6];
    float* out = (float*)d_out;

    static bool attr_set = false;
    if (!attr_set) {
        cudaFuncSetAttribute(k_front, cudaFuncAttributeMaxDynamicSharedMemorySize, 90112);
        attr_set = true;
    }

    k_front<<<256, 512, 88064>>>(values, query, keys);
    k_compute<<<512, 256>>>(W, b, lnw, lnb, out);
    k_bcast<<<4032, 256>>>(out);
}